// round 7
// baseline (speedup 1.0000x reference)
#include <cuda_runtime.h>
#include <math.h>

// Problem constants
#define B_   64
#define T_   4096
#define D_   512
#define NSEG 32                         // segments per batch
#define SEG_ROWS (T_ / NSEG)            // 128 rows per segment
#define NWARP 8
#define THREADS 256
#define ROWS_PER_ITER 4
#define NITER (SEG_ROWS / (NWARP * ROWS_PER_ITER))  // 4 iterations
#define TOTAL_SEGS (B_ * NSEG)          // 2048
#define GRID 304                        // 2 CTAs x 152 SMs (GB300), persistent

typedef unsigned long long u64;

// Per-(batch,segment) partial online-softmax state + completion counters.
__device__ float g_part_m[B_ * NSEG];
__device__ float g_part_l[B_ * NSEG];
__device__ float g_part_acc[B_ * NSEG * D_];
__device__ int   g_cnt[B_];             // zero-init; self-resetting each launch

__device__ __forceinline__ float neg_inf() { return __int_as_float(0xff800000); }

// ---- packed f32x2 helpers (FFMA2: PTX-only, halves fma-pipe issue) ----------
__device__ __forceinline__ u64 pack2(float lo, float hi) {
    u64 r; asm("mov.b64 %0,{%1,%2};" : "=l"(r) : "f"(lo), "f"(hi)); return r;
}
__device__ __forceinline__ void unpack2(u64 v, float& lo, float& hi) {
    asm("mov.b64 {%0,%1},%2;" : "=f"(lo), "=f"(hi) : "l"(v));
}
__device__ __forceinline__ u64 fma2(u64 a, u64 b, u64 c) {
    u64 d; asm("fma.rn.f32x2 %0,%1,%2,%3;" : "=l"(d) : "l"(a), "l"(b), "l"(c)); return d;
}
__device__ __forceinline__ u64 mul2(u64 a, u64 b) {
    u64 d; asm("mul.rn.f32x2 %0,%1,%2;" : "=l"(d) : "l"(a), "l"(b)); return d;
}
__device__ __forceinline__ u64 add2(u64 a, u64 b) {
    u64 d; asm("add.rn.f32x2 %0,%1,%2;" : "=l"(d) : "l"(a), "l"(b)); return d;
}

// -----------------------------------------------------------------------------
// Persistent fused kernel. 304 CTAs stride over 2048 segments. Each warp runs
// an independent online softmax, 4 rows (16 front-batched LDG.128 = 2KB) per
// item. The NEXT item's loads are issued right after the current buffer's last
// use — including across segment boundaries, so the per-segment epilogue
// (barriers + smem reduce + global writes) runs with 2KB/warp of next-segment
// loads already in flight. This closes the ~20% DRAM idle seen in R4/R6.
// -----------------------------------------------------------------------------
__global__ __launch_bounds__(THREADS, 2)
void attn_fused(const float* __restrict__ x,
                const float* __restrict__ v,
                float* __restrict__ ctx,     // d_out          [B*D]
                float* __restrict__ wts)     // d_out + B*D    [B*T]
{
    __shared__ float s_e[SEG_ROWS];          // segment energies
    __shared__ float s_m[NWARP], s_l[NWARP];
    __shared__ u64   s_acc[NWARP * 256];     // 16KB cross-warp reduce buffer
    __shared__ float s_scale[NSEG];          // merge-phase segment scales
    __shared__ int   s_last;

    const int tid  = threadIdx.x;
    const int warp = tid >> 5;
    const int lane = tid & 31;

    // v for this lane's 128 columns, packed as 8 f32x2 (loop-invariant)
    u64 vw[8];
    {
        const ulonglong2* v2 = reinterpret_cast<const ulonglong2*>(v);
        #pragma unroll
        for (int k = 0; k < 4; k++) {
            ulonglong2 t = v2[lane + 32 * k];
            vw[2*k] = t.x; vw[2*k+1] = t.y;
        }
    }

    int sid = blockIdx.x;                 // current segment id (persistent stride)
    u64 xd[4][8];                         // row buffer, persists across epilogue

    // ---- prefetch first item (sid, c=0) -------------------------------------
    {
        const int b0 = sid >> 5, s0 = sid & (NSEG - 1);
        const float* xp = x + ((size_t)b0 * T_ + s0 * SEG_ROWS
                               + warp * ROWS_PER_ITER) * D_;
        #pragma unroll
        for (int rr = 0; rr < 4; rr++) {
            const ulonglong2* xr =
                reinterpret_cast<const ulonglong2*>(xp + (size_t)rr * D_);
            #pragma unroll
            for (int k = 0; k < 4; k++) {
                ulonglong2 t = xr[lane + 32 * k];
                xd[rr][2*k] = t.x; xd[rr][2*k+1] = t.y;
            }
        }
    }

    for (;;) {
        const int b  = sid >> 5;
        const int s  = sid & (NSEG - 1);
        const int t0 = s * SEG_ROWS;

        u64 acc[8];
        #pragma unroll
        for (int i = 0; i < 8; i++) acc[i] = 0ull;
        float m = neg_inf();
        float l = 0.f;

        // ---- mainloop: 4 items, xd preloaded for item c on entry ------------
        #pragma unroll 1
        for (int c = 0; c < NITER; c++) {
            const int r0 = c * (NWARP * ROWS_PER_ITER) + warp * ROWS_PER_ITER;

            // Four independent dot products (packed FMA)
            u64 e2[4];
            #pragma unroll
            for (int rr = 0; rr < 4; rr++) {
                u64 a2 = 0ull;
                #pragma unroll
                for (int i = 0; i < 8; i++) a2 = fma2(xd[rr][i], vw[i], a2);
                e2[rr] = a2;
            }
            float e[4];
            #pragma unroll
            for (int rr = 0; rr < 4; rr++) {
                float lo, hi; unpack2(e2[rr], lo, hi);
                e[rr] = lo + hi;
            }
            // Interleaved butterfly reductions — all four latencies overlap
            #pragma unroll
            for (int o = 16; o; o >>= 1) {
                #pragma unroll
                for (int rr = 0; rr < 4; rr++)
                    e[rr] += __shfl_xor_sync(0xffffffffu, e[rr], o);
            }

            if (lane == 0) {
                #pragma unroll
                for (int rr = 0; rr < 4; rr++) s_e[r0 + rr] = e[rr];
            }

            const float cmax = fmaxf(fmaxf(e[0], e[1]), fmaxf(e[2], e[3]));
            if (cmax > m) {                    // warp-uniform rescale path
                const float sc = __expf(m - cmax);  // 0 on first item (m=-inf)
                const u64 sc2 = pack2(sc, sc);
                l *= sc;
                #pragma unroll
                for (int i = 0; i < 8; i++) acc[i] = mul2(acc[i], sc2);
                m = cmax;
            }
            #pragma unroll
            for (int rr = 0; rr < 4; rr++) {
                const float p = __expf(e[rr] - m);
                const u64 p2 = pack2(p, p);
                l += p;
                #pragma unroll
                for (int i = 0; i < 8; i++)
                    acc[i] = fma2(xd[rr][i], p2, acc[i]);   // last use of xd
            }

            // ---- prefetch next item (possibly next segment's c=0) -----------
            int nc = c + 1, nsid = sid;
            if (nc == NITER) { nc = 0; nsid = sid + GRID; }
            if (nsid < TOTAL_SEGS) {                // CTA-uniform predicate
                const int nb = nsid >> 5, ns = nsid & (NSEG - 1);
                const float* xp = x + ((size_t)nb * T_ + ns * SEG_ROWS
                                       + nc * (NWARP * ROWS_PER_ITER)
                                       + warp * ROWS_PER_ITER) * D_;
                #pragma unroll
                for (int rr = 0; rr < 4; rr++) {
                    const ulonglong2* xr =
                        reinterpret_cast<const ulonglong2*>(xp + (size_t)rr * D_);
                    #pragma unroll
                    for (int k = 0; k < 4; k++) {
                        ulonglong2 t = xr[lane + 32 * k];
                        xd[rr][2*k] = t.x; xd[rr][2*k+1] = t.y;
                    }
                }
            }
        }

        // ---- epilogue: runs with next segment's loads in flight -------------
        if (lane == 0) { s_m[warp] = m; s_l[warp] = l; }
        __syncthreads();

        float Mw = neg_inf();
        #pragma unroll
        for (int w = 0; w < NWARP; w++) Mw = fmaxf(Mw, s_m[w]);
        const float wsc = __expf(m - Mw);
        const u64 wsc2 = pack2(wsc, wsc);
        #pragma unroll
        for (int k = 0; k < 4; k++) {
            const int slot = 32 * k + lane;
            s_acc[warp * 256 + slot * 2    ] = mul2(acc[2*k],   wsc2);
            s_acc[warp * 256 + slot * 2 + 1] = mul2(acc[2*k+1], wsc2);
        }
        if (lane == 0) s_l[warp] = l * wsc;
        __syncthreads();

        const int bs = sid;
        if (tid < 128) {
            u64 a0 = 0ull, a1 = 0ull;
            #pragma unroll
            for (int w = 0; w < NWARP; w++) {
                a0 = add2(a0, s_acc[w * 256 + tid * 2    ]);
                a1 = add2(a1, s_acc[w * 256 + tid * 2 + 1]);
            }
            ulonglong2 o2; o2.x = a0; o2.y = a1;
            reinterpret_cast<ulonglong2*>(g_part_acc)[(size_t)bs * 128 + tid] = o2;
        }
        if (tid < SEG_ROWS) {
            wts[(size_t)b * T_ + t0 + tid] = s_e[tid];   // raw energies
        }
        if (tid == 0) {
            float L = 0.f;
            #pragma unroll
            for (int w = 0; w < NWARP; w++) L += s_l[w];
            g_part_m[bs] = Mw;
            g_part_l[bs] = L;
        }
        __syncthreads();

        // ---- last-CTA-per-batch detection -----------------------------------
        if (tid == 0) {
            __threadfence();
            const int old = atomicAdd(&g_cnt[b], 1);
            s_last = (old == NSEG - 1);
            if (s_last) atomicExch(&g_cnt[b], 0);   // reset for graph replay
        }
        __syncthreads();

        if (s_last) {
            __threadfence();
            // merge 32 segment partials for batch b
            if (tid < NSEG) s_scale[tid] = g_part_m[b * NSEG + tid];  // temp m_i
            __syncthreads();
            float Mb = neg_inf();
            #pragma unroll
            for (int i = 0; i < NSEG; i++) Mb = fmaxf(Mb, s_scale[i]);
            float Lb = 0.f;
            #pragma unroll
            for (int i = 0; i < NSEG; i++)
                Lb += g_part_l[b * NSEG + i] * __expf(s_scale[i] - Mb);
            const float invL = 1.f / Lb;
            __syncthreads();
            if (tid < NSEG) s_scale[tid] = __expf(s_scale[tid] - Mb) * invL;
            __syncthreads();

            // context[b, :] — 2 columns per thread
            #pragma unroll
            for (int h = 0; h < 2; h++) {
                const int col = tid + h * THREADS;
                float a = 0.f;
                #pragma unroll
                for (int i = 0; i < NSEG; i++)
                    a += g_part_acc[(size_t)(b * NSEG + i) * D_ + col] * s_scale[i];
                ctx[(size_t)b * D_ + col] = a;
            }

            // weights[b, :] = exp(e - Mb) * invL (vectorized in-place)
            float4* wb = reinterpret_cast<float4*>(wts + (size_t)b * T_);
            #pragma unroll
            for (int j = 0; j < 4; j++) {
                float4 w = wb[tid + j * THREADS];
                w.x = __expf(w.x - Mb) * invL;
                w.y = __expf(w.y - Mb) * invL;
                w.z = __expf(w.z - Mb) * invL;
                w.w = __expf(w.w - Mb) * invL;
                wb[tid + j * THREADS] = w;
            }
        }
        __syncthreads();   // protect smem reuse by next segment

        sid += GRID;
        if (sid >= TOTAL_SEGS) break;
    }
}

// -----------------------------------------------------------------------------
extern "C" void kernel_launch(void* const* d_in, const int* in_sizes, int n_in,
                              void* d_out, int out_size)
{
    const float* x = (const float*)d_in[0];   // encoder_outputs [B,T,D]
    const float* v = (const float*)d_in[1];   // attn_weights_param [D,1]
    float* out = (float*)d_out;
    float* ctx = out;                 // [B*D]
    float* wts = out + B_ * D_;       // [B*T]

    attn_fused<<<GRID, THREADS>>>(x, v, ctx, wts);
}

// round 8
// speedup vs baseline: 1.3591x; 1.3591x over previous
#include <cuda_runtime.h>
#include <math.h>

// Problem constants
#define B_   64
#define T_   4096
#define D_   512
#define NSEG 32                         // segments per batch
#define SEG_ROWS (T_ / NSEG)            // 128 rows per segment
#define NWARP 4
#define THREADS 128
#define ROWS_PER_ITER 4
#define NITER (SEG_ROWS / (NWARP * ROWS_PER_ITER))  // 8 iterations

typedef unsigned long long u64;

// Per-(batch,segment) partial online-softmax state + completion counters.
__device__ float g_part_m[B_ * NSEG];
__device__ float g_part_l[B_ * NSEG];
__device__ float g_part_acc[B_ * NSEG * D_];
__device__ int   g_cnt[B_];             // zero-init; self-resetting each launch

__device__ __forceinline__ float neg_inf() { return __int_as_float(0xff800000); }

// ---- packed f32x2 helpers (FFMA2: PTX-only, halves fma-pipe issue) ----------
__device__ __forceinline__ u64 pack2(float lo, float hi) {
    u64 r; asm("mov.b64 %0,{%1,%2};" : "=l"(r) : "f"(lo), "f"(hi)); return r;
}
__device__ __forceinline__ void unpack2(u64 v, float& lo, float& hi) {
    asm("mov.b64 {%0,%1},%2;" : "=f"(lo), "=f"(hi) : "l"(v));
}
__device__ __forceinline__ u64 fma2(u64 a, u64 b, u64 c) {
    u64 d; asm("fma.rn.f32x2 %0,%1,%2,%3;" : "=l"(d) : "l"(a), "l"(b), "l"(c)); return d;
}
__device__ __forceinline__ u64 mul2(u64 a, u64 b) {
    u64 d; asm("mul.rn.f32x2 %0,%1,%2;" : "=l"(d) : "l"(a), "l"(b)); return d;
}
__device__ __forceinline__ u64 add2(u64 a, u64 b) {
    u64 d; asm("add.rn.f32x2 %0,%1,%2;" : "=l"(d) : "l"(a), "l"(b)); return d;
}

// -----------------------------------------------------------------------------
// Single fused kernel (R6 mainloop, finer CTA granularity). One segment per
// CTA, 4 warps, each warp: independent online softmax over 32 rows, 4 rows
// per iteration (16 front-batched LDG.128 = 2KB MLP/warp; 4 CTAs/SM = 16
// warps, 32KB in flight/SM). Epilogue now stalls only 1/4 of the SM's warps
// at a time and reduces across 4 warps instead of 8. Energies are written
// directly to gmem from the mainloop (one STG.128 per warp per iter).
// -----------------------------------------------------------------------------
__global__ __launch_bounds__(THREADS, 4)
void attn_fused(const float* __restrict__ x,
                const float* __restrict__ v,
                float* __restrict__ ctx,     // d_out          [B*D]
                float* __restrict__ wts)     // d_out + B*D    [B*T]
{
    __shared__ float s_m[NWARP], s_l[NWARP];
    __shared__ u64   s_acc[NWARP * 256];     // 8KB cross-warp reduce buffer
    __shared__ float s_scale[NSEG];          // merge-phase segment scales
    __shared__ int   s_last;

    const int tid  = threadIdx.x;
    const int warp = tid >> 5;
    const int lane = tid & 31;
    const int b    = blockIdx.x / NSEG;
    const int s    = blockIdx.x % NSEG;
    const int t0   = s * SEG_ROWS;

    const float* xb = x + ((size_t)b * T_ + t0) * D_;

    // v for this lane's 128 columns, packed as 8 f32x2 (loop-invariant)
    u64 vw[8];
    {
        const ulonglong2* v2 = reinterpret_cast<const ulonglong2*>(v);
        #pragma unroll
        for (int k = 0; k < 4; k++) {
            ulonglong2 t = v2[lane + 32 * k];
            vw[2*k] = t.x; vw[2*k+1] = t.y;
        }
    }

    u64 acc[8];
    #pragma unroll
    for (int i = 0; i < 8; i++) acc[i] = 0ull;   // packed {0.f, 0.f}
    float m = neg_inf();
    float l = 0.f;

    // ---- mainloop: barrier-free per-warp online softmax, 4 rows/iter --------
    #pragma unroll 1
    for (int c = 0; c < NITER; c++) {
        const int r0 = c * (NWARP * ROWS_PER_ITER) + warp * ROWS_PER_ITER;

        // Front-batch 16 independent LDG.128 (2KB in flight per warp)
        u64 xd[4][8];
        #pragma unroll
        for (int rr = 0; rr < 4; rr++) {
            const ulonglong2* xr =
                reinterpret_cast<const ulonglong2*>(xb + (size_t)(r0 + rr) * D_);
            #pragma unroll
            for (int k = 0; k < 4; k++) {
                ulonglong2 t = xr[lane + 32 * k];
                xd[rr][2*k] = t.x; xd[rr][2*k+1] = t.y;
            }
        }

        // Four independent dot products (packed FMA)
        u64 e2[4];
        #pragma unroll
        for (int rr = 0; rr < 4; rr++) {
            u64 a2 = 0ull;
            #pragma unroll
            for (int i = 0; i < 8; i++) a2 = fma2(xd[rr][i], vw[i], a2);
            e2[rr] = a2;
        }
        float e[4];
        #pragma unroll
        for (int rr = 0; rr < 4; rr++) {
            float lo, hi; unpack2(e2[rr], lo, hi);
            e[rr] = lo + hi;
        }
        // Interleaved butterfly reductions — all four latencies overlap
        #pragma unroll
        for (int o = 16; o; o >>= 1) {
            #pragma unroll
            for (int rr = 0; rr < 4; rr++)
                e[rr] += __shfl_xor_sync(0xffffffffu, e[rr], o);
        }

        // Raw energies straight to gmem: rows r0..r0+3 are consecutive.
        if (lane == 0) {
            float4 ev = make_float4(e[0], e[1], e[2], e[3]);
            *reinterpret_cast<float4*>(wts + (size_t)b * T_ + t0 + r0) = ev;
        }

        const float cmax = fmaxf(fmaxf(e[0], e[1]), fmaxf(e[2], e[3]));
        if (cmax > m) {                      // warp-uniform rescale path
            const float sc = __expf(m - cmax);   // 0 on first iter (m = -inf)
            const u64 sc2 = pack2(sc, sc);
            l *= sc;
            #pragma unroll
            for (int i = 0; i < 8; i++) acc[i] = mul2(acc[i], sc2);
            m = cmax;
        }
        #pragma unroll
        for (int rr = 0; rr < 4; rr++) {
            const float p = __expf(e[rr] - m);
            const u64 p2 = pack2(p, p);
            l += p;
            #pragma unroll
            for (int i = 0; i < 8; i++)
                acc[i] = fma2(xd[rr][i], p2, acc[i]);
        }
    }

    // ---- in-CTA merge of 4 warp partials ------------------------------------
    if (lane == 0) { s_m[warp] = m; s_l[warp] = l; }
    __syncthreads();

    float Mw = neg_inf();
    #pragma unroll
    for (int w = 0; w < NWARP; w++) Mw = fmaxf(Mw, s_m[w]);
    const float wsc = __expf(m - Mw);
    const u64 wsc2 = pack2(wsc, wsc);
    #pragma unroll
    for (int k = 0; k < 4; k++) {
        const int slot = 32 * k + lane;
        s_acc[warp * 256 + slot * 2    ] = mul2(acc[2*k],   wsc2);
        s_acc[warp * 256 + slot * 2 + 1] = mul2(acc[2*k+1], wsc2);
    }
    if (lane == 0) s_l[warp] = l * wsc;
    __syncthreads();

    const int bs = blockIdx.x;
    // 128 threads cover 256 u64 slots (2 each)
    {
        u64 a0 = 0ull, a1 = 0ull;
        #pragma unroll
        for (int w = 0; w < NWARP; w++) {
            a0 = add2(a0, s_acc[w * 256 + tid * 2    ]);
            a1 = add2(a1, s_acc[w * 256 + tid * 2 + 1]);
        }
        ulonglong2 o2; o2.x = a0; o2.y = a1;
        reinterpret_cast<ulonglong2*>(g_part_acc)[(size_t)bs * 128 + tid] = o2;
    }
    if (tid == 0) {
        float L = 0.f;
        #pragma unroll
        for (int w = 0; w < NWARP; w++) L += s_l[w];
        g_part_m[bs] = Mw;
        g_part_l[bs] = L;
    }
    __syncthreads();

    // ---- last-CTA-per-batch detection (threadFenceReduction pattern) --------
    if (tid == 0) {
        __threadfence();
        const int old = atomicAdd(&g_cnt[b], 1);
        s_last = (old == NSEG - 1);
        if (s_last) atomicExch(&g_cnt[b], 0);   // reset for next graph replay
    }
    __syncthreads();
    if (!s_last) return;
    __threadfence();

    // ---- merge 32 segment partials for batch b ------------------------------
    if (tid < NSEG) s_scale[tid] = g_part_m[b * NSEG + tid];  // temp: m_i
    __syncthreads();
    float Mb = neg_inf();
    #pragma unroll
    for (int i = 0; i < NSEG; i++) Mb = fmaxf(Mb, s_scale[i]);
    float Lb = 0.f;
    #pragma unroll
    for (int i = 0; i < NSEG; i++)
        Lb += g_part_l[b * NSEG + i] * __expf(s_scale[i] - Mb);
    const float invL = 1.f / Lb;
    __syncthreads();
    if (tid < NSEG) s_scale[tid] = __expf(s_scale[tid] - Mb) * invL;
    __syncthreads();

    // context[b, :] — 4 columns per thread
    #pragma unroll
    for (int h = 0; h < 4; h++) {
        const int col = tid + h * THREADS;
        float a = 0.f;
        #pragma unroll
        for (int i = 0; i < NSEG; i++)
            a += g_part_acc[(size_t)(b * NSEG + i) * D_ + col] * s_scale[i];
        ctx[(size_t)b * D_ + col] = a;
    }

    // weights[b, :] = exp(e - Mb) * invL   (vectorized in-place, 8 f4/thread)
    {
        float4* wb = reinterpret_cast<float4*>(wts + (size_t)b * T_);
        #pragma unroll
        for (int j = 0; j < 8; j++) {
            float4 w = wb[tid + j * THREADS];
            w.x = __expf(w.x - Mb) * invL;
            w.y = __expf(w.y - Mb) * invL;
            w.z = __expf(w.z - Mb) * invL;
            w.w = __expf(w.w - Mb) * invL;
            wb[tid + j * THREADS] = w;
        }
    }
}

// -----------------------------------------------------------------------------
extern "C" void kernel_launch(void* const* d_in, const int* in_sizes, int n_in,
                              void* d_out, int out_size)
{
    const float* x = (const float*)d_in[0];   // encoder_outputs [B,T,D]
    const float* v = (const float*)d_in[1];   // attn_weights_param [D,1]
    float* out = (float*)d_out;
    float* ctx = out;                 // [B*D]
    float* wts = out + B_ * D_;       // [B*T]

    attn_fused<<<B_ * NSEG, THREADS>>>(x, v, ctx, wts);
}